// round 13
// baseline (speedup 1.0000x reference)
#include <cuda_runtime.h>
#include <cuda_fp16.h>
#include <cstdint>

#define N_NODES 20000
#define D_IN 512
#define D_OUT 64
#define N_EDGES 160000

// ---------------------------------------------------------------------------
// device globals (no allocation allowed)
// ---------------------------------------------------------------------------
// buf0: [x_h fp16: 20MB | h1_h fp16: 20MB]; later z fp32 (5MB) overwrites x_h
__device__ float g_buf0[(size_t)N_NODES * D_IN];
__device__ float g_buf1[(size_t)N_NODES * D_IN];   // h2_h fp16
__device__ int g_deg[N_NODES];
__device__ int g_off[N_NODES + 1];
__device__ int g_cursor[N_NODES];
__device__ int g_adj[N_EDGES];
__device__ __half g_w1_h[D_IN * D_IN];
__device__ __half g_w2_h[D_OUT * D_IN];

// ---------------------------------------------------------------------------
// CSR build
// ---------------------------------------------------------------------------
__global__ void csr_zero_deg(int* deg) {
    int i = blockIdx.x * blockDim.x + threadIdx.x;
    if (i < N_NODES) deg[i] = 0;
}
__global__ void csr_hist(const int* __restrict__ dst, int* __restrict__ deg) {
    int e = blockIdx.x * blockDim.x + threadIdx.x;
    if (e < N_EDGES) atomicAdd(&deg[dst[e]], 1);
}
__global__ void csr_scan(const int* __restrict__ deg, int* __restrict__ off,
                         int* __restrict__ cursor) {
    __shared__ int ssum[1024];
    const int t = threadIdx.x;
    const int ITEMS = 20;
    int base = t * ITEMS;
    int local[ITEMS];
    int s = 0;
#pragma unroll
    for (int i = 0; i < ITEMS; i++) {
        int idx = base + i;
        int v = (idx < N_NODES) ? deg[idx] : 0;
        local[i] = s;
        s += v;
    }
    ssum[t] = s;
    __syncthreads();
    for (int d = 1; d < 1024; d <<= 1) {
        int v = (t >= d) ? ssum[t - d] : 0;
        __syncthreads();
        ssum[t] += v;
        __syncthreads();
    }
    int prev = (t > 0) ? ssum[t - 1] : 0;
#pragma unroll
    for (int i = 0; i < ITEMS; i++) {
        int idx = base + i;
        if (idx < N_NODES) {
            int o = prev + local[i];
            off[idx] = o;
            cursor[idx] = o;
        }
    }
    if (t == 1023) off[N_NODES] = ssum[1023];
}
__global__ void csr_fill(const int* __restrict__ src, const int* __restrict__ dst,
                         int* __restrict__ cursor, int* __restrict__ adj) {
    int e = blockIdx.x * blockDim.x + threadIdx.x;
    if (e < N_EDGES) {
        int p = atomicAdd(&cursor[dst[e]], 1);
        adj[p] = src[e];
    }
}

// ---------------------------------------------------------------------------
// Round fp32 -> fp16 (scalar for W; float4 -> uint2 for x)
// ---------------------------------------------------------------------------
__global__ void round_w(const float* __restrict__ w, __half* __restrict__ h, int n) {
    int i = blockIdx.x * blockDim.x + threadIdx.x;
    if (i < n) h[i] = __float2half_rn(w[i]);
}
__global__ void round_x(const float4* __restrict__ x, uint2* __restrict__ xh, int n4) {
    int i = blockIdx.x * blockDim.x + threadIdx.x;
    if (i >= n4) return;
    float4 v = x[i];
    union { __half2 h2[2]; uint2 u; } o;
    o.h2[0] = __floats2half2_rn(v.x, v.y);
    o.h2[1] = __floats2half2_rn(v.z, v.w);
    xh[i] = o.u;
}

// ---------------------------------------------------------------------------
// Gather propagate on fp16 rows (fp32 accumulate, fp16 out).
// One 128-thread block per node; each thread owns one uint2 (4 fp16).
// ---------------------------------------------------------------------------
__global__ void gather_prop_h(const uint2* __restrict__ x,  // [N, 128] uint2
                              const int* __restrict__ off,
                              const int* __restrict__ adj,
                              uint2* __restrict__ out) {
    const int node = blockIdx.x;
    const int t = threadIdx.x;
    int b = off[node];
    int e = off[node + 1];
    float4 acc = make_float4(0.f, 0.f, 0.f, 0.f);
    int i = b;
    for (; i + 1 < e; i += 2) {
        uint2 v0 = x[(size_t)adj[i] * 128 + t];
        uint2 v1 = x[(size_t)adj[i + 1] * 128 + t];
        float2 a = __half22float2(*reinterpret_cast<__half2*>(&v0.x));
        float2 b2 = __half22float2(*reinterpret_cast<__half2*>(&v0.y));
        float2 c = __half22float2(*reinterpret_cast<__half2*>(&v1.x));
        float2 d = __half22float2(*reinterpret_cast<__half2*>(&v1.y));
        acc.x += a.x + c.x;
        acc.y += a.y + c.y;
        acc.z += b2.x + d.x;
        acc.w += b2.y + d.y;
    }
    if (i < e) {
        uint2 v0 = x[(size_t)adj[i] * 128 + t];
        float2 a = __half22float2(*reinterpret_cast<__half2*>(&v0.x));
        float2 b2 = __half22float2(*reinterpret_cast<__half2*>(&v0.y));
        acc.x += a.x;
        acc.y += a.y;
        acc.z += b2.x;
        acc.w += b2.y;
    }
    union { __half2 h2[2]; uint2 u; } o;
    o.h2[0] = __floats2half2_rn(acc.x, acc.y);
    o.h2[1] = __floats2half2_rn(acc.z, acc.w);
    out[(size_t)node * 128 + t] = o.u;
}

// ---------------------------------------------------------------------------
// Gather propagate 64-wide + fused log_softmax (one warp per node, z fp32)
// ---------------------------------------------------------------------------
__global__ void gather64_softmax(const float* __restrict__ z,
                                 const int* __restrict__ off,
                                 const int* __restrict__ adj,
                                 float* __restrict__ out) {
    const int node = blockIdx.x * (blockDim.x >> 5) + (threadIdx.x >> 5);
    const int lane = threadIdx.x & 31;
    if (node >= N_NODES) return;
    int b = off[node];
    int e = off[node + 1];
    float a0 = 0.f, a1 = 0.f;
    for (int i = b; i < e; i++) {
        const float* zp = z + (size_t)adj[i] * D_OUT;
        a0 += zp[lane];
        a1 += zp[lane + 32];
    }
    float mx = fmaxf(a0, a1);
#pragma unroll
    for (int o = 16; o > 0; o >>= 1)
        mx = fmaxf(mx, __shfl_xor_sync(0xffffffffu, mx, o));
    float s = expf(a0 - mx) + expf(a1 - mx);
#pragma unroll
    for (int o = 16; o > 0; o >>= 1)
        s += __shfl_xor_sync(0xffffffffu, s, o);
    float l = mx + logf(s);
    float* p = out + (size_t)node * D_OUT;
    p[lane] = a0 - l;
    p[lane + 32] = a1 - l;
}

// ---------------------------------------------------------------------------
// mma.sync helpers
// ---------------------------------------------------------------------------
__device__ __forceinline__ void mma_fp16(float* d, const uint32_t* a,
                                         const uint32_t* b) {
    asm volatile(
        "mma.sync.aligned.m16n8k16.row.col.f32.f16.f16.f32 "
        "{%0,%1,%2,%3}, {%4,%5,%6,%7}, {%8,%9}, {%0,%1,%2,%3};"
        : "+f"(d[0]), "+f"(d[1]), "+f"(d[2]), "+f"(d[3])
        : "r"(a[0]), "r"(a[1]), "r"(a[2]), "r"(a[3]), "r"(b[0]), "r"(b[1]));
}

__device__ __forceinline__ void ldmx4(uint32_t* r, uint32_t addr) {
    asm volatile(
        "ldmatrix.sync.aligned.m8n8.x4.shared.b16 {%0,%1,%2,%3}, [%4];"
        : "=r"(r[0]), "=r"(r[1]), "=r"(r[2]), "=r"(r[3])
        : "r"(addr));
}

// ---------------------------------------------------------------------------
// Pure-fp16 GEMM via mma.sync: C[M,N] = A[M,512] * B[N,512]^T
// A, B fp16 in global; fp32 accumulate; out fp16 (OUT_HALF) or fp32.
// CTA tile 128 x BN, BK=32, 8 warps each 32 x (BN/2).
// Register-prefetch: LDG(kc+1) issued before MMA(kc).
// smem rows 64B data + 16B pad -> conflict-free ldmatrix.
// ---------------------------------------------------------------------------
#define LDS_STRIDE 80

template <int BN, bool RELU, bool OUT_HALF>
__global__ __launch_bounds__(256)
void gemm_fp16(const __half* __restrict__ A,
               const __half* __restrict__ B,
               void* __restrict__ C, int M, int N) {
    constexpr int NI = BN / 16;
    constexpr int NG = BN / 32;
    constexpr int SM_A = 0;
    constexpr int SM_B = 128 * LDS_STRIDE;
    constexpr int SM_TOTAL = SM_B + BN * LDS_STRIDE;
    constexpr int BPR = 256 / BN;        // threads per B row
    constexpr int BVEC = 4 / BPR;        // uint4 per thread in B tile (row=64B)

    __shared__ __align__(16) char smem[SM_TOTAL];
    const int tid = threadIdx.x;
    const int lane = tid & 31;
    const int wid = tid >> 5;
    const int wm = wid & 3;
    const int wn = wid >> 2;
    const int m0 = blockIdx.x * 128;
    const int n0 = blockIdx.y * BN;

    const uint32_t sb = (uint32_t)__cvta_generic_to_shared(smem);

    float acc[2][NI][4];
#pragma unroll
    for (int i = 0; i < 2; i++)
#pragma unroll
        for (int j = 0; j < NI; j++)
#pragma unroll
            for (int k = 0; k < 4; k++) acc[i][j][k] = 0.f;

    // A: row = tid/2 (0..127), half = tid%2; 32B (2 uint4) per thread
    const int ar = tid >> 1;
    const int ah = tid & 1;
    const bool arow_ok = (m0 + ar) < M;
    // B: row = tid/BPR, chunk = tid%BPR; BVEC uint4 per thread
    const int br = tid / BPR;
    const int bq = tid % BPR;

    const uint32_t a_lm = sb + (uint32_t)((wm * 32 + (lane & 15)) * LDS_STRIDE +
                                          (lane >> 4) * 16);
    const uint32_t b_lm = sb + SM_B +
        (uint32_t)((wn * (BN / 2) + (lane & 15)) * LDS_STRIDE + (lane >> 4) * 16);

    uint4 av[2];
    uint4 bv[BVEC];

    auto load_tile = [&](int kc) {
        if (arow_ok) {
            const uint4* ap = reinterpret_cast<const uint4*>(
                A + (size_t)(m0 + ar) * D_IN + kc * 32 + ah * 16);
            av[0] = ap[0];
            av[1] = ap[1];
        } else {
            av[0] = make_uint4(0, 0, 0, 0);
            av[1] = make_uint4(0, 0, 0, 0);
        }
        const uint4* bp = reinterpret_cast<const uint4*>(
            B + (size_t)(n0 + br) * D_IN + kc * 32 + bq * (8 * BVEC));
#pragma unroll
        for (int i = 0; i < BVEC; i++) bv[i] = bp[i];
    };

    load_tile(0);

    for (int kc = 0; kc < 16; kc++) {
        __syncthreads();

        {
            char* pa = smem + SM_A + ar * LDS_STRIDE + ah * 32;
            *reinterpret_cast<uint4*>(pa) = av[0];
            *reinterpret_cast<uint4*>(pa + 16) = av[1];
        }
        {
            char* pb = smem + SM_B + br * LDS_STRIDE + bq * (16 * BVEC);
#pragma unroll
            for (int i = 0; i < BVEC; i++)
                *reinterpret_cast<uint4*>(pb + i * 16) = bv[i];
        }
        __syncthreads();

        if (kc + 1 < 16) load_tile(kc + 1);

#pragma unroll
        for (int ks = 0; ks < 2; ks++) {
            uint32_t aF[2][4], bF[NG][4];
#pragma unroll
            for (int mi = 0; mi < 2; mi++)
                ldmx4(aF[mi], a_lm + mi * 16 * LDS_STRIDE + ks * 32);
#pragma unroll
            for (int ng = 0; ng < NG; ng++)
                ldmx4(bF[ng], b_lm + ng * 16 * LDS_STRIDE + ks * 32);
#pragma unroll
            for (int mi = 0; mi < 2; mi++) {
#pragma unroll
                for (int ng = 0; ng < NG; ng++) {
#pragma unroll
                    for (int nb = 0; nb < 2; nb++) {
                        int ni = ng * 2 + nb;
                        uint32_t b2[2] = {bF[ng][nb], bF[ng][nb + 2]};
                        mma_fp16(acc[mi][ni], aF[mi], b2);
                    }
                }
            }
        }
    }

    // epilogue
    const int g = lane >> 2;
    const int t4 = lane & 3;
#pragma unroll
    for (int mi = 0; mi < 2; mi++) {
#pragma unroll
        for (int ni = 0; ni < NI; ni++) {
            int col = n0 + wn * (BN / 2) + ni * 8 + t4 * 2;
            int row0 = m0 + wm * 32 + mi * 16 + g;
            int row1 = row0 + 8;
            float2 v0 = make_float2(acc[mi][ni][0], acc[mi][ni][1]);
            float2 v1 = make_float2(acc[mi][ni][2], acc[mi][ni][3]);
            if (RELU) {
                v0.x = fmaxf(v0.x, 0.f); v0.y = fmaxf(v0.y, 0.f);
                v1.x = fmaxf(v1.x, 0.f); v1.y = fmaxf(v1.y, 0.f);
            }
            if (OUT_HALF) {
                __half* Cp = (__half*)C;
                union { __half2 h; uint32_t u; } o0, o1;
                o0.h = __floats2half2_rn(v0.x, v0.y);
                o1.h = __floats2half2_rn(v1.x, v1.y);
                if (row0 < M)
                    *reinterpret_cast<uint32_t*>(Cp + (size_t)row0 * N + col) = o0.u;
                if (row1 < M)
                    *reinterpret_cast<uint32_t*>(Cp + (size_t)row1 * N + col) = o1.u;
            } else {
                float* Cp = (float*)C;
                if (row0 < M)
                    *reinterpret_cast<float2*>(Cp + (size_t)row0 * N + col) = v0;
                if (row1 < M)
                    *reinterpret_cast<float2*>(Cp + (size_t)row1 * N + col) = v1;
            }
        }
    }
}

// ---------------------------------------------------------------------------
// launch
// ---------------------------------------------------------------------------
extern "C" void kernel_launch(void* const* d_in, const int* in_sizes, int n_in,
                              void* d_out, int out_size) {
    const float* x = (const float*)d_in[0];
    const int* ei = (const int*)d_in[1];
    const float* W1 = (const float*)d_in[2];
    const float* W2 = (const float*)d_in[3];
    float* out = (float*)d_out;

    const int* src = ei;
    const int* dst = ei + N_EDGES;

    float *buf0, *buf1;
    int *deg, *off, *cursor, *adj;
    __half *w1h, *w2h;
    cudaGetSymbolAddress((void**)&buf0, g_buf0);
    cudaGetSymbolAddress((void**)&buf1, g_buf1);
    cudaGetSymbolAddress((void**)&deg, g_deg);
    cudaGetSymbolAddress((void**)&off, g_off);
    cudaGetSymbolAddress((void**)&cursor, g_cursor);
    cudaGetSymbolAddress((void**)&adj, g_adj);
    cudaGetSymbolAddress((void**)&w1h, g_w1_h);
    cudaGetSymbolAddress((void**)&w2h, g_w2_h);

    // fp16 views into buf0/buf1
    __half* xh = (__half*)buf0;                               // 20MB
    __half* h1h = (__half*)buf0 + (size_t)N_NODES * D_IN;     // 20MB (upper half)
    __half* h2h = (__half*)buf1;
    float* z = buf0;   // overwrites xh region after GEMM1 (5MB)

    const int n4 = N_NODES * D_IN / 4;  // 2,560,000

    // rounding (cheap, independent)
    round_w<<<(D_IN * D_IN + 255) / 256, 256>>>(W1, w1h, D_IN * D_IN);
    round_w<<<(D_OUT * D_IN + 255) / 256, 256>>>(W2, w2h, D_OUT * D_IN);
    round_x<<<(n4 + 255) / 256, 256>>>((const float4*)x, (uint2*)xh, n4);

    // CSR build (by destination)
    csr_zero_deg<<<(N_NODES + 255) / 256, 256>>>(deg);
    csr_hist<<<(N_EDGES + 255) / 256, 256>>>(dst, deg);
    csr_scan<<<1, 1024>>>(deg, off, cursor);
    csr_fill<<<(N_EDGES + 255) / 256, 256>>>(src, dst, cursor, adj);

    const int n_mtiles = (N_NODES + 127) / 128;  // 157

    // propagate 1 (fp16): h1 = segment_sum(x[src] -> dst)
    gather_prop_h<<<N_NODES, 128>>>((const uint2*)xh, off, adj, (uint2*)h1h);

    // GEMM1 + ReLU: h2 = relu(h1 @ W1^T), fp16 out
    {
        dim3 grid(n_mtiles, D_IN / 128);
        gemm_fp16<128, true, true><<<grid, 256>>>(h1h, w1h, h2h, N_NODES, D_IN);
    }

    // GEMM2 first (P commutes with right-mul): z = h2 @ W2^T, fp32 out
    {
        dim3 grid(n_mtiles, 1);
        gemm_fp16<64, false, false><<<grid, 256>>>(h2h, w2h, z, N_NODES, D_OUT);
    }

    // propagate 2 (64-wide) + fused log_softmax
    gather64_softmax<<<(N_NODES + 7) / 8, 256>>>(z, off, adj, out);
}

// round 14
// speedup vs baseline: 1.1161x; 1.1161x over previous
#include <cuda_runtime.h>
#include <cuda_fp16.h>
#include <cstdint>

#define N_NODES 20000
#define D_IN 512
#define D_OUT 64
#define N_EDGES 160000

// ---------------------------------------------------------------------------
// device globals (no allocation allowed)
// ---------------------------------------------------------------------------
__device__ float g_buf0[(size_t)N_NODES * D_IN];   // h1 fp32, later z fp32
__device__ float g_buf1[(size_t)N_NODES * D_IN];   // h2 fp32
__device__ __half g_x_h[(size_t)N_NODES * D_IN];   // x rounded to fp16
__device__ int g_deg[N_NODES];
__device__ int g_off[N_NODES + 1];
__device__ int g_cursor[N_NODES];
__device__ int g_adj[N_EDGES];
__device__ __half g_w1_h[D_IN * D_IN];
__device__ __half g_w2_h[D_OUT * D_IN];

// ---------------------------------------------------------------------------
// CSR build
// ---------------------------------------------------------------------------
__global__ void csr_zero_deg(int* deg) {
    int i = blockIdx.x * blockDim.x + threadIdx.x;
    if (i < N_NODES) deg[i] = 0;
}
__global__ void csr_hist(const int* __restrict__ dst, int* __restrict__ deg) {
    int e = blockIdx.x * blockDim.x + threadIdx.x;
    if (e < N_EDGES) atomicAdd(&deg[dst[e]], 1);
}
__global__ void csr_scan(const int* __restrict__ deg, int* __restrict__ off,
                         int* __restrict__ cursor) {
    __shared__ int ssum[1024];
    const int t = threadIdx.x;
    const int ITEMS = 20;
    int base = t * ITEMS;
    int local[ITEMS];
    int s = 0;
#pragma unroll
    for (int i = 0; i < ITEMS; i++) {
        int idx = base + i;
        int v = (idx < N_NODES) ? deg[idx] : 0;
        local[i] = s;
        s += v;
    }
    ssum[t] = s;
    __syncthreads();
    for (int d = 1; d < 1024; d <<= 1) {
        int v = (t >= d) ? ssum[t - d] : 0;
        __syncthreads();
        ssum[t] += v;
        __syncthreads();
    }
    int prev = (t > 0) ? ssum[t - 1] : 0;
#pragma unroll
    for (int i = 0; i < ITEMS; i++) {
        int idx = base + i;
        if (idx < N_NODES) {
            int o = prev + local[i];
            off[idx] = o;
            cursor[idx] = o;
        }
    }
    if (t == 1023) off[N_NODES] = ssum[1023];
}
__global__ void csr_fill(const int* __restrict__ src, const int* __restrict__ dst,
                         int* __restrict__ cursor, int* __restrict__ adj) {
    int e = blockIdx.x * blockDim.x + threadIdx.x;
    if (e < N_EDGES) {
        int p = atomicAdd(&cursor[dst[e]], 1);
        adj[p] = src[e];
    }
}

// ---------------------------------------------------------------------------
// Merged rounding: x (float4->uint2), W1, W2 (float4->uint2) in one kernel
// ---------------------------------------------------------------------------
#define N4_X (N_NODES * D_IN / 4)     // 2,560,000
#define N4_W1 (D_IN * D_IN / 4)       // 65,536
#define N4_W2 (D_OUT * D_IN / 4)      // 8,192
#define N4_ALL (N4_X + N4_W1 + N4_W2)

__device__ __forceinline__ uint2 f4_to_h4(float4 v) {
    union { __half2 h2[2]; uint2 u; } o;
    o.h2[0] = __floats2half2_rn(v.x, v.y);
    o.h2[1] = __floats2half2_rn(v.z, v.w);
    return o.u;
}

__global__ void round_all(const float4* __restrict__ x,
                          const float4* __restrict__ w1,
                          const float4* __restrict__ w2,
                          uint2* __restrict__ xh,
                          uint2* __restrict__ w1h,
                          uint2* __restrict__ w2h) {
    int i = blockIdx.x * blockDim.x + threadIdx.x;
    if (i < N4_X) {
        xh[i] = f4_to_h4(x[i]);
    } else if (i < N4_X + N4_W1) {
        int j = i - N4_X;
        w1h[j] = f4_to_h4(w1[j]);
    } else if (i < N4_ALL) {
        int j = i - N4_X - N4_W1;
        w2h[j] = f4_to_h4(w2[j]);
    }
}

// ---------------------------------------------------------------------------
// Gather propagate: fp16 x in, fp32 accumulate, fp32 h1 out.
// One 128-thread block per node; thread owns 4 halfs in, float4 out.
// ---------------------------------------------------------------------------
__global__ void gather_prop_h(const uint2* __restrict__ xh,  // [N, 128] uint2
                              const int* __restrict__ off,
                              const int* __restrict__ adj,
                              float4* __restrict__ out) {    // [N, 128] float4
    const int node = blockIdx.x;
    const int t = threadIdx.x;
    int b = off[node];
    int e = off[node + 1];
    float4 acc = make_float4(0.f, 0.f, 0.f, 0.f);
    int i = b;
    for (; i + 1 < e; i += 2) {
        union { uint2 u; __half2 h[2]; } v0, v1;
        v0.u = xh[(size_t)adj[i] * 128 + t];
        v1.u = xh[(size_t)adj[i + 1] * 128 + t];
        float2 a = __half22float2(v0.h[0]);
        float2 bb = __half22float2(v0.h[1]);
        float2 c = __half22float2(v1.h[0]);
        float2 d = __half22float2(v1.h[1]);
        acc.x += a.x + c.x;
        acc.y += a.y + c.y;
        acc.z += bb.x + d.x;
        acc.w += bb.y + d.y;
    }
    if (i < e) {
        union { uint2 u; __half2 h[2]; } v0;
        v0.u = xh[(size_t)adj[i] * 128 + t];
        float2 a = __half22float2(v0.h[0]);
        float2 bb = __half22float2(v0.h[1]);
        acc.x += a.x;
        acc.y += a.y;
        acc.z += bb.x;
        acc.w += bb.y;
    }
    out[(size_t)node * 128 + t] = acc;
}

// ---------------------------------------------------------------------------
// Gather propagate 64-wide + fused log_softmax (one warp per node, z fp32)
// ---------------------------------------------------------------------------
__global__ void gather64_softmax(const float* __restrict__ z,
                                 const int* __restrict__ off,
                                 const int* __restrict__ adj,
                                 float* __restrict__ out) {
    const int node = blockIdx.x * (blockDim.x >> 5) + (threadIdx.x >> 5);
    const int lane = threadIdx.x & 31;
    if (node >= N_NODES) return;
    int b = off[node];
    int e = off[node + 1];
    float a0 = 0.f, a1 = 0.f;
    for (int i = b; i < e; i++) {
        const float* zp = z + (size_t)adj[i] * D_OUT;
        a0 += zp[lane];
        a1 += zp[lane + 32];
    }
    float mx = fmaxf(a0, a1);
#pragma unroll
    for (int o = 16; o > 0; o >>= 1)
        mx = fmaxf(mx, __shfl_xor_sync(0xffffffffu, mx, o));
    float s = expf(a0 - mx) + expf(a1 - mx);
#pragma unroll
    for (int o = 16; o > 0; o >>= 1)
        s += __shfl_xor_sync(0xffffffffu, s, o);
    float l = mx + logf(s);
    float* p = out + (size_t)node * D_OUT;
    p[lane] = a0 - l;
    p[lane + 32] = a1 - l;
}

// ---------------------------------------------------------------------------
// mma.sync helpers (fp16 inputs, fp32 accumulate)
// ---------------------------------------------------------------------------
__device__ __forceinline__ void mma_fp16(float* d, const uint32_t* a,
                                         const uint32_t* b) {
    asm volatile(
        "mma.sync.aligned.m16n8k16.row.col.f32.f16.f16.f32 "
        "{%0,%1,%2,%3}, {%4,%5,%6,%7}, {%8,%9}, {%0,%1,%2,%3};"
        : "+f"(d[0]), "+f"(d[1]), "+f"(d[2]), "+f"(d[3])
        : "r"(a[0]), "r"(a[1]), "r"(a[2]), "r"(a[3]), "r"(b[0]), "r"(b[1]));
}

__device__ __forceinline__ void ldmx4(uint32_t* r, uint32_t addr) {
    asm volatile(
        "ldmatrix.sync.aligned.m8n8.x4.shared.b16 {%0,%1,%2,%3}, [%4];"
        : "=r"(r[0]), "=r"(r[1]), "=r"(r[2]), "=r"(r[3])
        : "r"(addr));
}

// ---------------------------------------------------------------------------
// fp16 2-term split GEMM via mma.sync: C[M,N] = A[M,512] * B[N,512]^T
// A fp32 -> fp16 hi+lo inline (A exact to ~2^-22); B pre-rounded fp16.
// C = Ah*Bh + Al*Bh; error = A*(B - Bh) ~ 2^-12 RMS.
// CTA tile 128 x BN, BK=32, 8 warps each 32 x (BN/2).
// Register-prefetch: LDG(kc+1) issued before MMA(kc).
// ---------------------------------------------------------------------------
#define LDS_STRIDE 80

template <int BN, bool RELU>
__global__ __launch_bounds__(256)
void gemm_mma(const float* __restrict__ A,
              const __half* __restrict__ Bh,
              float* __restrict__ C, int M, int N) {
    constexpr int NI = BN / 16;
    constexpr int NG = BN / 32;
    constexpr int SM_AH = 0;
    constexpr int SM_AL = 128 * LDS_STRIDE;
    constexpr int SM_BH = 2 * 128 * LDS_STRIDE;
    constexpr int SM_TOTAL = SM_BH + BN * LDS_STRIDE;
    constexpr int BPR = 256 / BN;        // threads per B row
    constexpr int BVEC = 4 / BPR;        // uint4 per thread (B tile 64B/row)

    __shared__ __align__(16) char smem[SM_TOTAL];
    const int tid = threadIdx.x;
    const int lane = tid & 31;
    const int wid = tid >> 5;
    const int wm = wid & 3;
    const int wn = wid >> 2;
    const int m0 = blockIdx.x * 128;
    const int n0 = blockIdx.y * BN;

    const uint32_t sb = (uint32_t)__cvta_generic_to_shared(smem);

    float acc[2][NI][4];
#pragma unroll
    for (int i = 0; i < 2; i++)
#pragma unroll
        for (int j = 0; j < NI; j++)
#pragma unroll
            for (int k = 0; k < 4; k++) acc[i][j][k] = 0.f;

    const int ar = tid >> 1;
    const int ah = tid & 1;
    const bool arow_ok = (m0 + ar) < M;
    const int br = tid / BPR;
    const int bq = tid % BPR;

    const uint32_t a_lm = sb + (uint32_t)((wm * 32 + (lane & 15)) * LDS_STRIDE +
                                          (lane >> 4) * 16);
    const uint32_t b_lm = sb + SM_BH +
        (uint32_t)((wn * (BN / 2) + (lane & 15)) * LDS_STRIDE + (lane >> 4) * 16);

    float4 av[4];
    uint4 bhv[BVEC];

    auto load_tile = [&](int kc) {
        if (arow_ok) {
            const float4* ap = reinterpret_cast<const float4*>(
                A + (size_t)(m0 + ar) * D_IN + kc * 32 + ah * 16);
#pragma unroll
            for (int i = 0; i < 4; i++) av[i] = ap[i];
        } else {
#pragma unroll
            for (int i = 0; i < 4; i++) av[i] = make_float4(0.f, 0.f, 0.f, 0.f);
        }
        const uint4* bh = reinterpret_cast<const uint4*>(
            Bh + (size_t)(n0 + br) * D_IN + kc * 32 + bq * (8 * BVEC));
#pragma unroll
        for (int i = 0; i < BVEC; i++) bhv[i] = bh[i];
    };

    load_tile(0);

    for (int kc = 0; kc < 16; kc++) {
        __syncthreads();

        // STS: convert A fp32 -> fp16 hi/lo
        {
            union { __half2 h2[8]; uint4 u[2]; } hi, lo;
            const float* f = reinterpret_cast<const float*>(av);
#pragma unroll
            for (int j = 0; j < 8; j++) {
                float a0 = f[2 * j], a1 = f[2 * j + 1];
                __half h0 = __float2half_rn(a0);
                __half h1 = __float2half_rn(a1);
                hi.h2[j] = __halves2half2(h0, h1);
                lo.h2[j] = __halves2half2(
                    __float2half_rn(a0 - __half2float(h0)),
                    __float2half_rn(a1 - __half2float(h1)));
            }
            char* pa = smem + ar * LDS_STRIDE + ah * 32;
            *reinterpret_cast<uint4*>(pa + SM_AH) = hi.u[0];
            *reinterpret_cast<uint4*>(pa + SM_AH + 16) = hi.u[1];
            *reinterpret_cast<uint4*>(pa + SM_AL) = lo.u[0];
            *reinterpret_cast<uint4*>(pa + SM_AL + 16) = lo.u[1];
        }
        {
            char* pb = smem + SM_BH + br * LDS_STRIDE + bq * (16 * BVEC);
#pragma unroll
            for (int i = 0; i < BVEC; i++)
                *reinterpret_cast<uint4*>(pb + i * 16) = bhv[i];
        }
        __syncthreads();

        if (kc + 1 < 16) load_tile(kc + 1);

        // compute: 2 ksteps of 16
#pragma unroll
        for (int ks = 0; ks < 2; ks++) {
            uint32_t aH[2][4], aL[2][4], bH[NG][4];
#pragma unroll
            for (int mi = 0; mi < 2; mi++) {
                uint32_t addr = a_lm + mi * 16 * LDS_STRIDE + ks * 32;
                ldmx4(aH[mi], addr);
                ldmx4(aL[mi], addr + (SM_AL - SM_AH));
            }
#pragma unroll
            for (int ng = 0; ng < NG; ng++) {
                uint32_t addr = b_lm + ng * 16 * LDS_STRIDE + ks * 32;
                ldmx4(bH[ng], addr);
            }
#pragma unroll
            for (int mi = 0; mi < 2; mi++) {
#pragma unroll
                for (int ng = 0; ng < NG; ng++) {
#pragma unroll
                    for (int nb = 0; nb < 2; nb++) {
                        int ni = ng * 2 + nb;
                        uint32_t bh2[2] = {bH[ng][nb], bH[ng][nb + 2]};
                        mma_fp16(acc[mi][ni], aH[mi], bh2);
                        mma_fp16(acc[mi][ni], aL[mi], bh2);
                    }
                }
            }
        }
    }

    // epilogue
    const int g = lane >> 2;
    const int t4 = lane & 3;
#pragma unroll
    for (int mi = 0; mi < 2; mi++) {
#pragma unroll
        for (int ni = 0; ni < NI; ni++) {
            int col = n0 + wn * (BN / 2) + ni * 8 + t4 * 2;
            int row0 = m0 + wm * 32 + mi * 16 + g;
            int row1 = row0 + 8;
            float2 v0 = make_float2(acc[mi][ni][0], acc[mi][ni][1]);
            float2 v1 = make_float2(acc[mi][ni][2], acc[mi][ni][3]);
            if (RELU) {
                v0.x = fmaxf(v0.x, 0.f); v0.y = fmaxf(v0.y, 0.f);
                v1.x = fmaxf(v1.x, 0.f); v1.y = fmaxf(v1.y, 0.f);
            }
            if (row0 < M)
                *reinterpret_cast<float2*>(C + (size_t)row0 * N + col) = v0;
            if (row1 < M)
                *reinterpret_cast<float2*>(C + (size_t)row1 * N + col) = v1;
        }
    }
}

// ---------------------------------------------------------------------------
// launch
// ---------------------------------------------------------------------------
extern "C" void kernel_launch(void* const* d_in, const int* in_sizes, int n_in,
                              void* d_out, int out_size) {
    const float* x = (const float*)d_in[0];
    const int* ei = (const int*)d_in[1];
    const float* W1 = (const float*)d_in[2];
    const float* W2 = (const float*)d_in[3];
    float* out = (float*)d_out;

    const int* src = ei;
    const int* dst = ei + N_EDGES;

    float *h1, *h2;
    int *deg, *off, *cursor, *adj;
    __half *w1h, *w2h, *xh;
    cudaGetSymbolAddress((void**)&h1, g_buf0);
    cudaGetSymbolAddress((void**)&h2, g_buf1);
    cudaGetSymbolAddress((void**)&deg, g_deg);
    cudaGetSymbolAddress((void**)&off, g_off);
    cudaGetSymbolAddress((void**)&cursor, g_cursor);
    cudaGetSymbolAddress((void**)&adj, g_adj);
    cudaGetSymbolAddress((void**)&w1h, g_w1_h);
    cudaGetSymbolAddress((void**)&w2h, g_w2_h);
    cudaGetSymbolAddress((void**)&xh, g_x_h);

    // merged rounding: x, W1, W2 -> fp16
    round_all<<<(N4_ALL + 255) / 256, 256>>>(
        (const float4*)x, (const float4*)W1, (const float4*)W2,
        (uint2*)xh, (uint2*)w1h, (uint2*)w2h);

    // CSR build (by destination)
    csr_zero_deg<<<(N_NODES + 255) / 256, 256>>>(deg);
    csr_hist<<<(N_EDGES + 255) / 256, 256>>>(dst, deg);
    csr_scan<<<1, 1024>>>(deg, off, cursor);
    csr_fill<<<(N_EDGES + 255) / 256, 256>>>(src, dst, cursor, adj);

    const int n_mtiles = (N_NODES + 127) / 128;  // 157

    // propagate 1: h1(fp32) = segment_sum(x_h[src] -> dst)
    gather_prop_h<<<N_NODES, 128>>>((const uint2*)xh, off, adj, (float4*)h1);

    // GEMM1 + ReLU: h2 = relu(h1 @ W1^T)   [20000, 512]
    {
        dim3 grid(n_mtiles, D_IN / 128);
        gemm_mma<128, true><<<grid, 256>>>(h1, w1h, h2, N_NODES, D_IN);
    }

    // GEMM2 first (P commutes with right-mul): z = h2 @ W2^T  [20000, 64]
    {
        dim3 grid(n_mtiles, 1);
        gemm_mma<64, false><<<grid, 256>>>(h2, w2h, h1, N_NODES, D_OUT);
    }

    // propagate 2 (64-wide) + fused log_softmax
    gather64_softmax<<<(N_NODES + 7) / 8, 256>>>(h1, off, adj, out);
}